// round 3
// baseline (speedup 1.0000x reference)
#include <cuda_runtime.h>

#define NN 100000
#define EE 3200000
#define DINF 256
#define DHID 256
#define DO 64
#define KHOPS 10
#define NB_SCAN 98   // ceil(100000/1024)

// ---------------- scratch (device globals; no allocation allowed) -------------
__device__ __align__(16) float g_hidden[(size_t)NN * DHID];           // 102.4 MB
__device__ __align__(16) float g_h[(size_t)(KHOPS + 1) * NN * DO];    // 281.6 MB
__device__ float g_dinv[NN];
__device__ int   g_deg[NN];
__device__ int   g_cursor[NN];
__device__ int   g_off[NN + 1];
__device__ int2  g_csr[EE];                                           // {src, bitcast(norm)}
__device__ int   g_bsum[NB_SCAN];
__device__ int   g_is64;

// ---------------- edge dtype detection ---------------------------------------
// int64 little-endian node ids (< 2^31) have all-zero odd 32-bit words.
// int32 ids in [0,100000) are nonzero with prob ~1-1e-5 per word.
__global__ void k_detect(const int* __restrict__ w) {
    __shared__ int nz;
    if (threadIdx.x == 0) nz = 0;
    __syncthreads();
    int local = 0;
    for (int i = threadIdx.x; i < 2048; i += 256)
        if (w[2 * i + 1] != 0) local = 1;
    if (local) atomicAdd(&nz, 1);
    __syncthreads();
    if (threadIdx.x == 0) g_is64 = (nz == 0) ? 1 : 0;
}

__device__ __forceinline__ int edge_at(const void* eiv, long long idx) {
    int v;
    if (g_is64) v = (int)((const long long*)eiv)[idx];
    else        v = ((const int*)eiv)[idx];
    return min(max(v, 0), NN - 1);   // clamp: never trap on a bad guess
}

// ---------------- degree / normalization ------------------------------------
__global__ void k_init() {
    int i = blockIdx.x * blockDim.x + threadIdx.x;
    if (i < NN) { g_deg[i] = 1; g_cursor[i] = 0; }   // deg starts at 1: self-loop
}

__global__ void k_count(const void* __restrict__ eiv) {
    int e = blockIdx.x * blockDim.x + threadIdx.x;
    if (e < EE) atomicAdd(&g_deg[edge_at(eiv, (long long)EE + e)], 1);
}

__global__ void k_dinv() {
    int i = blockIdx.x * blockDim.x + threadIdx.x;
    if (i < NN) g_dinv[i] = rsqrtf((float)g_deg[i]);
}

// ---------------- exclusive scan of (deg-1) over N ---------------------------
__global__ void k_scanA() {
    int tid = threadIdx.x;
    int i = blockIdx.x * 1024 + tid;
    int v = (i < NN) ? (g_deg[i] - 1) : 0;
    int lane = tid & 31, wid = tid >> 5;
    int x = v;
    #pragma unroll
    for (int o = 1; o < 32; o <<= 1) {
        int t = __shfl_up_sync(0xffffffffu, x, o);
        if (lane >= o) x += t;
    }
    __shared__ int wsum[32];
    if (lane == 31) wsum[wid] = x;
    __syncthreads();
    if (wid == 0) {
        int y = wsum[lane];
        #pragma unroll
        for (int o = 1; o < 32; o <<= 1) {
            int t = __shfl_up_sync(0xffffffffu, y, o);
            if (lane >= o) y += t;
        }
        wsum[lane] = y;
    }
    __syncthreads();
    int incl = x + (wid > 0 ? wsum[wid - 1] : 0);
    if (i < NN) g_off[i] = incl - v;                // block-local exclusive
    if (tid == 1023) g_bsum[blockIdx.x] = incl;     // block total
}

__global__ void k_scanB() {
    if (threadIdx.x == 0) {
        int s = 0;
        for (int i = 0; i < NB_SCAN; i++) { int t = g_bsum[i]; g_bsum[i] = s; s += t; }
    }
}

__global__ void k_scanC() {
    int i = blockIdx.x * 1024 + threadIdx.x;
    if (i < NN) g_off[i] += g_bsum[blockIdx.x];
    if (i == 0) g_off[NN] = EE;
}

// ---------------- CSR fill (dest-sorted edges with weights) ------------------
__global__ void k_fill(const void* __restrict__ eiv) {
    int e = blockIdx.x * blockDim.x + threadIdx.x;
    if (e < EE) {
        int r = edge_at(eiv, e);
        int c = edge_at(eiv, (long long)EE + e);
        float w = g_dinv[r] * g_dinv[c];
        int p = g_off[c] + atomicAdd(&g_cursor[c], 1);
        if (p < EE) g_csr[p] = make_int2(r, __float_as_int(w));
    }
}

// ---------------- fp32 tiled GEMM: C = op(A@B + bias) ------------------------
// BM=128, BN=64, BK=16, 256 threads, 8x4 outputs/thread. A row length fixed 256.
// FIRST: A = x param (relu, C = g_hidden, Ncols=256)
// !FIRST: A = g_hidden (no relu, C = g_h hop-0 slice, Ncols=64)
template<bool FIRST>
__global__ void __launch_bounds__(256) k_gemm(
    const float* __restrict__ Ain, const float* __restrict__ B,
    const float* __restrict__ bias) {
    const int BM = 128, BK = 16;
    const int Ncols = FIRST ? DHID : DO;
    const float* __restrict__ A = FIRST ? Ain : g_hidden;
    float* __restrict__ C = FIRST ? g_hidden : g_h;

    __shared__ float As[BK][BM];
    __shared__ float Bs[BK][64];
    int tid = threadIdx.x;
    int rowBase = blockIdx.x * BM;
    int nBase = blockIdx.y * 64;
    int ty = tid >> 4, tx = tid & 15;

    float acc[8][4];
    #pragma unroll
    for (int i = 0; i < 8; i++)
        #pragma unroll
        for (int j = 0; j < 4; j++) acc[i][j] = 0.f;

    for (int k0 = 0; k0 < 256; k0 += BK) {
        // A tile: 128x16 = 512 float4, 2 per thread, stored transposed
        #pragma unroll
        for (int q = 0; q < 2; q++) {
            int L = tid * 2 + q;
            int aRow = L >> 2, aK4 = L & 3;
            int gRow = rowBase + aRow; if (gRow >= NN) gRow = NN - 1;
            float4 v = *(const float4*)(A + (size_t)gRow * 256 + k0 + aK4 * 4);
            As[aK4 * 4 + 0][aRow] = v.x;
            As[aK4 * 4 + 1][aRow] = v.y;
            As[aK4 * 4 + 2][aRow] = v.z;
            As[aK4 * 4 + 3][aRow] = v.w;
        }
        // B tile: 16x64 = 256 float4, 1 per thread
        {
            int bK = tid >> 4, bN4 = tid & 15;
            float4 v = *(const float4*)(B + (size_t)(k0 + bK) * Ncols + nBase + bN4 * 4);
            *((float4*)&Bs[bK][bN4 * 4]) = v;
        }
        __syncthreads();
        #pragma unroll
        for (int kk = 0; kk < BK; kk++) {
            float4 A0 = *((const float4*)&As[kk][ty * 8]);
            float4 A1 = *((const float4*)&As[kk][ty * 8 + 4]);
            float4 Bv = *((const float4*)&Bs[kk][tx * 4]);
            float a[8] = {A0.x, A0.y, A0.z, A0.w, A1.x, A1.y, A1.z, A1.w};
            float b[4] = {Bv.x, Bv.y, Bv.z, Bv.w};
            #pragma unroll
            for (int i = 0; i < 8; i++)
                #pragma unroll
                for (int j = 0; j < 4; j++)
                    acc[i][j] = fmaf(a[i], b[j], acc[i][j]);
        }
        __syncthreads();
    }
    float4 bb = *(const float4*)(bias + nBase + tx * 4);
    #pragma unroll
    for (int i = 0; i < 8; i++) {
        int row = rowBase + ty * 8 + i;
        if (row < NN) {
            float4 o;
            o.x = acc[i][0] + bb.x;
            o.y = acc[i][1] + bb.y;
            o.z = acc[i][2] + bb.z;
            o.w = acc[i][3] + bb.w;
            if (FIRST) {
                o.x = fmaxf(o.x, 0.f); o.y = fmaxf(o.y, 0.f);
                o.z = fmaxf(o.z, 0.f); o.w = fmaxf(o.w, 0.f);
            }
            *(float4*)(C + (size_t)row * Ncols + nBase + tx * 4) = o;
        }
    }
}

// ---------------- propagation hop: gather over dest-CSR ----------------------
// warp per node; 16 lanes x float4 cover 64 features; two edge streams (halves)
__global__ void __launch_bounds__(256) k_hop(int hop) {
    int gw = (blockIdx.x * blockDim.x + threadIdx.x) >> 5;
    if (gw >= NN) return;
    int lane = threadIdx.x & 31;
    int hf = lane >> 4, sub = lane & 15;
    const float4* __restrict__ hprev = (const float4*)(g_h + (size_t)hop * NN * DO);
    float4* __restrict__ hnew = (float4*)(g_h + (size_t)(hop + 1) * NN * DO);
    int start = g_off[gw], end = g_off[gw + 1];

    float ax = 0.f, ay = 0.f, az = 0.f, aw = 0.f;
    for (int base = start; base < end; base += 32) {
        int i = base + lane;
        int2 meta = make_int2(0, 0);        // lanes past end contribute w=0
        if (i < end) meta = g_csr[i];
        int lim = end - base; if (lim > 32) lim = 32;
        for (int j2 = 0; j2 < lim; j2 += 2) {   // uniform loop bounds for shfl
            int j = (j2 + hf) & 31;
            int s = __shfl_sync(0xffffffffu, meta.x, j);
            float w = __int_as_float(__shfl_sync(0xffffffffu, meta.y, j));
            float4 v = __ldg(&hprev[s * 16 + sub]);
            ax = fmaf(w, v.x, ax); ay = fmaf(w, v.y, ay);
            az = fmaf(w, v.z, az); aw = fmaf(w, v.w, aw);
        }
    }
    // merge the two edge streams
    ax += __shfl_xor_sync(0xffffffffu, ax, 16);
    ay += __shfl_xor_sync(0xffffffffu, ay, 16);
    az += __shfl_xor_sync(0xffffffffu, az, 16);
    aw += __shfl_xor_sync(0xffffffffu, aw, 16);
    if (hf == 0) {
        float d = g_dinv[gw];
        float w = d * d;                    // self-loop term
        float4 v = __ldg(&hprev[gw * 16 + sub]);
        hnew[gw * 16 + sub] = make_float4(fmaf(w, v.x, ax), fmaf(w, v.y, ay),
                                          fmaf(w, v.z, az), fmaf(w, v.w, aw));
    }
}

// ---------------- adaptive hop pooling epilogue ------------------------------
__global__ void __launch_bounds__(256) k_pool(const float* __restrict__ pw,
                                              const float* __restrict__ pb,
                                              float* __restrict__ out) {
    int gw = (blockIdx.x * blockDim.x + threadIdx.x) >> 5;
    if (gw >= NN) return;
    int lane = threadIdx.x & 31;
    float2 w2 = ((const float2*)pw)[lane];
    float bias = pb[0];
    float ox = 0.f, oy = 0.f;
    #pragma unroll
    for (int k = 0; k <= KHOPS; k++) {
        const float2* hp = (const float2*)(g_h + (size_t)k * NN * DO + (size_t)gw * DO);
        float2 v = __ldg(&hp[lane]);
        float p = v.x * w2.x + v.y * w2.y;
        #pragma unroll
        for (int o = 16; o; o >>= 1) p += __shfl_xor_sync(0xffffffffu, p, o);
        float sc = 1.f / (1.f + expf(-(p + bias)));
        ox = fmaf(sc, v.x, ox);
        oy = fmaf(sc, v.y, oy);
    }
    ((float2*)(out + (size_t)gw * DO))[lane] = make_float2(ox, oy);
}

// ---------------- launch -----------------------------------------------------
extern "C" void kernel_launch(void* const* d_in, const int* in_sizes, int n_in,
                              void* d_out, int out_size) {
    const float* x  = (const float*)d_in[0];
    const void*  ei = d_in[1];
    const float* W1 = (const float*)d_in[2];
    const float* b1 = (const float*)d_in[3];
    const float* W2 = (const float*)d_in[4];
    const float* b2 = (const float*)d_in[5];
    const float* pw = (const float*)d_in[6];
    const float* pb = (const float*)d_in[7];
    float* out = (float*)d_out;

    k_detect<<<1, 256>>>((const int*)ei);
    k_init <<<(NN + 255) / 256, 256>>>();
    k_count<<<(EE + 255) / 256, 256>>>(ei);
    k_dinv <<<(NN + 255) / 256, 256>>>();
    k_scanA<<<NB_SCAN, 1024>>>();
    k_scanB<<<1, 32>>>();
    k_scanC<<<NB_SCAN, 1024>>>();
    k_fill <<<(EE + 255) / 256, 256>>>(ei);

    k_gemm<true> <<<dim3((NN + 127) / 128, DHID / 64), 256>>>(x, W1, b1);
    k_gemm<false><<<dim3((NN + 127) / 128, 1),         256>>>(nullptr, W2, b2);

    for (int k = 0; k < KHOPS; k++)
        k_hop<<<NN / 8, 256>>>(k);

    k_pool<<<NN / 8, 256>>>(pw, pb, out);
}